// round 12
// baseline (speedup 1.0000x reference)
#include <cuda_runtime.h>
#include <cstdint>
#include <math.h>

#define Bc 2
#define Hc 16
#define Sc 2048
#define Dc 72

static constexpr int NROWS = Bc * Hc * Sc;   // 65536

__device__ __align__(16) float g_q[(size_t)NROWS * Dc];
__device__ __align__(16) float g_k[(size_t)NROWS * Dc];

// ---------------------------------------------------------------------------
// helpers
// ---------------------------------------------------------------------------
__device__ __forceinline__ uint32_t f2tf(float x) {
    uint32_t r;
    asm("cvt.rna.tf32.f32 %0, %1;" : "=r"(r) : "f"(x));
    return r;
}

// D += A(16x8,row) * B(8x8,col)   tf32, fp32 accum
__device__ __forceinline__ void mma8(float& d0, float& d1, float& d2, float& d3,
                                     uint32_t a0, uint32_t a1, uint32_t a2, uint32_t a3,
                                     uint32_t b0, uint32_t b1) {
    asm volatile("mma.sync.aligned.m16n8k8.row.col.f32.tf32.tf32.f32 "
                 "{%0,%1,%2,%3}, {%4,%5,%6,%7}, {%8,%9}, {%0,%1,%2,%3};"
                 : "+f"(d0), "+f"(d1), "+f"(d2), "+f"(d3)
                 : "r"(a0), "r"(a1), "r"(a2), "r"(a3), "r"(b0), "r"(b1));
}

// exp(s) for bounded |s|, FMA-pipe only (no MUFU). rel err ~2e-6.
__device__ __forceinline__ float fast_exp(float s) {
    const float L2E = 1.4426950408889634f;
    float x = s * L2E;
    int   ni = __float2int_rn(x);
    float f  = x - (float)ni;
    float p  = 0.0013333558f;
    p = fmaf(p, f, 0.0096181290f);
    p = fmaf(p, f, 0.0555041087f);
    p = fmaf(p, f, 0.2402265069f);
    p = fmaf(p, f, 0.6931471806f);
    p = fmaf(p, f, 1.0f);
    return p * __int_as_float((ni + 127) << 23);
}

// ---------------------------------------------------------------------------
// Preprocess: theta + rotary + L2 norm for q and k. One warp per (b,h,s) row.
// Also zeroes the output rows with s < 576 (no valid keys).
// ---------------------------------------------------------------------------
__global__ void prep_kernel(const float* __restrict__ q, const float* __restrict__ k,
                            const float* __restrict__ pos, const float* __restrict__ pos_orig,
                            const float* __restrict__ time_, const float* __restrict__ freqs,
                            const float* __restrict__ t_freqs, const float* __restrict__ scale,
                            float* __restrict__ out) {
    int warp = threadIdx.x >> 5, lane = threadIdx.x & 31;
    int row = blockIdx.x * 8 + warp;
    int s  = row & (Sc - 1);
    int bh = row >> 11;
    int h  = bh & (Hc - 1);
    int b  = bh >> 4;

    const float* qr = q + (size_t)row * Dc;
    const float* kr = k + (size_t)row * Dc;

    __shared__ float sq[8][Dc], sk[8][Dc];
    for (int e = lane; e < Dc; e += 32) { sq[warp][e] = qr[e]; sk[warp][e] = kr[e]; }
    __syncwarp();

    if (s < 576) {   // zero invalid output rows (replaces zero_kernel)
        float4* orow = (float4*)(out + (size_t)row * Dc);
        if (lane < 18) orow[lane] = make_float4(0.f, 0.f, 0.f, 0.f);
    }

    int ps = (b * Sc + s) * 2;
    float px  = 2.f * pos[ps]       - 1.f;
    float py  = 2.f * pos[ps + 1]   - 1.f;
    float pxo = 2.f * pos_orig[ps]     - 1.f;
    float pyo = 2.f * pos_orig[ps + 1] - 1.f;
    float tm  = time_[b * Sc + s];

    float oq[3], ok[3];
    float ssq = 0.f, ssk = 0.f;
    #pragma unroll
    for (int slot = 0; slot < 3; slot++) {
        int j = lane + slot * 32;
        if (j < Dc) {
            float xq = sq[warp][j], xk = sk[warp][j];
            if (j < 60) {
                int jj = (j < 30) ? j : j - 30;
                int seg = jj / 6, i = jj % 6;
                float coef, fr;
                if      (seg == 0) { coef = pyo; fr = freqs[96 + h * 6 + i]; }
                else if (seg == 1) { coef = py;  fr = freqs[96 + h * 6 + i]; }
                else if (seg == 2) { coef = pxo; fr = freqs[h * 6 + i]; }
                else if (seg == 3) { coef = px;  fr = freqs[h * 6 + i]; }
                else               { coef = tm;  fr = t_freqs[h * 6 + i]; }
                float th = coef * fr, c, sn;
                sincosf(th, &sn, &c);
                if (j < 30) {
                    oq[slot] = xq * c - sq[warp][j + 30] * sn;
                    ok[slot] = xk * c - sk[warp][j + 30] * sn;
                } else {
                    oq[slot] = xq * c + sq[warp][j - 30] * sn;
                    ok[slot] = xk * c + sk[warp][j - 30] * sn;
                }
            } else { oq[slot] = xq; ok[slot] = xk; }
            ssq += oq[slot] * oq[slot];
            ssk += ok[slot] * ok[slot];
        } else { oq[slot] = 0.f; ok[slot] = 0.f; }
    }
    #pragma unroll
    for (int off = 16; off; off >>= 1) {
        ssq += __shfl_xor_sync(0xffffffffu, ssq, off);
        ssk += __shfl_xor_sync(0xffffffffu, ssk, off);
    }
    float ss = sqrtf(scale[h]);
    float rq = ss * rsqrtf(ssq + 1e-6f);
    float rk = ss * rsqrtf(ssk + 1e-6f);
    #pragma unroll
    for (int slot = 0; slot < 3; slot++) {
        int j = lane + slot * 32;
        if (j < Dc) {
            g_q[(size_t)row * Dc + j] = oq[slot] * rq;
            g_k[(size_t)row * Dc + j] = ok[slot] * rk;
        }
    }
}

// ---------------------------------------------------------------------------
// Attention with warp-level tf32 mma.sync. 128-query tiles, 256 threads
// (8 warps x 16 q-rows). K/V tiles of 64 keys amortized over 128 queries.
// grid = (12 q-tiles from q=576, 32 bh). Bounded scores -> no softmax max.
// ---------------------------------------------------------------------------
static constexpr int KVS = 76;          // padded row stride (conflict-free B frags)

__global__ void __launch_bounds__(256)
attn_kernel(const float* __restrict__ v, float* __restrict__ out) {
    __shared__ uint32_t sm[2 * 64 * KVS];           // 38912 B
    uint32_t* Ks = sm;
    uint32_t* Vs = sm + 64 * KVS;
    float*    Qs = (float*)sm;                       // 128x72 staging overlaps K/V

    int tid = threadIdx.x, wid = tid >> 5, lane = tid & 31;
    int g = lane >> 2, c = lane & 3;
    int m  = blockIdx.x;                 // 0..11
    int bh = blockIdx.y;
    int q0 = 576 + 128 * m;
    size_t base = (size_t)bh * Sc;

    // ---- stage Q tile (rows clamped for the m=11 tail), build A-fragments ----
    {
        for (int i = tid; i < 128 * 18; i += 256) {
            int r = i / 18, cc = i % 18;
            int qr = q0 + r; if (qr > 2047) qr = 2047;
            ((float4*)Qs)[i] = ((const float4*)(g_q + (base + qr) * Dc))[cc];
        }
    }
    __syncthreads();
    uint32_t aq[9][4];
    {
        const float* qb = Qs + (wid * 16) * 72;
        #pragma unroll
        for (int kb = 0; kb < 9; kb++) {
            aq[kb][0] = f2tf(qb[g * 72       + kb * 8 + c]);
            aq[kb][1] = f2tf(qb[(g + 8) * 72 + kb * 8 + c]);
            aq[kb][2] = f2tf(qb[g * 72       + kb * 8 + 4 + c]);
            aq[kb][3] = f2tf(qb[(g + 8) * 72 + kb * 8 + 4 + c]);
        }
    }
    __syncthreads();   // done reading Qs before K/V overwrite it

    float o[9][4];
    #pragma unroll
    for (int i = 0; i < 9; i++) { o[i][0] = o[i][1] = o[i][2] = o[i][3] = 0.f; }
    float l_lo = 0.f, l_hi = 0.f;

    bool causal = (m < 4);
    int nt = causal ? (11 + 2 * m) : 17;
    int qrow_lo = q0 + wid * 16 + g;
    int qrow_hi = qrow_lo + 8;

    for (int kt = 0; kt < nt; kt++) {
        // ---- load K,V tile as tf32 bit patterns ----
        {
            const float4* ksrc = (const float4*)(g_k + (base + (size_t)kt * 64) * Dc);
            const float4* vsrc = (const float4*)(v   + (base + (size_t)kt * 64) * Dc);
            for (int i = tid; i < 64 * 18; i += 256) {
                int r = i / 18, c4 = (i % 18) * 4;
                float4 kv = ksrc[i];
                float4 vv = vsrc[i];
                *(uint4*)(Ks + r * KVS + c4) =
                    make_uint4(f2tf(kv.x), f2tf(kv.y), f2tf(kv.z), f2tf(kv.w));
                *(uint4*)(Vs + r * KVS + c4) =
                    make_uint4(f2tf(vv.x), f2tf(vv.y), f2tf(vv.z), f2tf(vv.w));
            }
        }
        __syncthreads();

        bool lastmask = causal && (kt >= nt - 2);   // diagonal spans last two tiles
        int kb_glob = kt * 64;

        #pragma unroll
        for (int nb = 0; nb < 8; nb++) {
            // S block: 16 q-rows x 8 keys
            float d0 = 0.f, d1 = 0.f, d2 = 0.f, d3 = 0.f;
            const uint32_t* kbp = Ks + (nb * 8 + g) * KVS + c;
            #pragma unroll
            for (int kb = 0; kb < 9; kb++) {
                uint32_t b0 = kbp[kb * 8];
                uint32_t b1 = kbp[kb * 8 + 4];
                mma8(d0, d1, d2, d3, aq[kb][0], aq[kb][1], aq[kb][2], aq[kb][3], b0, b1);
            }
            // exp (+ diagonal mask on last causal tiles)
            float p0 = fast_exp(d0), p1 = fast_exp(d1);
            float p2 = fast_exp(d2), p3 = fast_exp(d3);
            if (lastmask) {
                int col = kb_glob + nb * 8 + 2 * c;
                if (col     > qrow_lo) p0 = 0.f;
                if (col + 1 > qrow_lo) p1 = 0.f;
                if (col     > qrow_hi) p2 = 0.f;
                if (col + 1 > qrow_hi) p3 = 0.f;
            }
            l_lo += p0 + p1;
            l_hi += p2 + p3;

            // repack D-layout -> A-layout (P fragment) via shuffles
            int srcA = (lane & ~3) + (c >> 1);
            int srcB = srcA + 2;
            float v00 = __shfl_sync(0xffffffffu, p0, srcA);
            float v01 = __shfl_sync(0xffffffffu, p1, srcA);
            float v10 = __shfl_sync(0xffffffffu, p2, srcA);
            float v11 = __shfl_sync(0xffffffffu, p3, srcA);
            float w00 = __shfl_sync(0xffffffffu, p0, srcB);
            float w01 = __shfl_sync(0xffffffffu, p1, srcB);
            float w10 = __shfl_sync(0xffffffffu, p2, srcB);
            float w11 = __shfl_sync(0xffffffffu, p3, srcB);
            bool odd = (c & 1);
            uint32_t pa0 = f2tf(odd ? v01 : v00);
            uint32_t pa1 = f2tf(odd ? v11 : v10);
            uint32_t pa2 = f2tf(odd ? w01 : w00);
            uint32_t pa3 = f2tf(odd ? w11 : w10);

            // O += P(16x8keys) @ V(8keys x 72dims)
            const uint32_t* vbp = Vs + (nb * 8 + c) * KVS + g;
            #pragma unroll
            for (int db = 0; db < 9; db++) {
                uint32_t b0 = vbp[db * 8];
                uint32_t b1 = vbp[4 * KVS + db * 8];
                mma8(o[db][0], o[db][1], o[db][2], o[db][3], pa0, pa1, pa2, pa3, b0, b1);
            }
        }
        __syncthreads();
    }

    // reduce l across the 4 lanes sharing a row group
    l_lo += __shfl_xor_sync(0xffffffffu, l_lo, 1);
    l_lo += __shfl_xor_sync(0xffffffffu, l_lo, 2);
    l_hi += __shfl_xor_sync(0xffffffffu, l_hi, 1);
    l_hi += __shfl_xor_sync(0xffffffffu, l_hi, 2);

    if (!causal) {   // dense rows: add the self key k == q
        int rlo = (qrow_lo < 2048) ? qrow_lo : 2047;
        int rhi = (qrow_hi < 2048) ? qrow_hi : 2047;
        const float2* qlo = (const float2*)(g_q + (base + rlo) * Dc);
        const float2* klo = (const float2*)(g_k + (base + rlo) * Dc);
        const float2* qhi = (const float2*)(g_q + (base + rhi) * Dc);
        const float2* khi = (const float2*)(g_k + (base + rhi) * Dc);
        float sl = 0.f, sh = 0.f;
        #pragma unroll
        for (int nb = 0; nb < 9; nb++) {
            float2 a = qlo[4 * nb + c], b = klo[4 * nb + c];
            sl += a.x * b.x + a.y * b.y;
            float2 e = qhi[4 * nb + c], f = khi[4 * nb + c];
            sh += e.x * f.x + e.y * f.y;
        }
        sl += __shfl_xor_sync(0xffffffffu, sl, 1);
        sl += __shfl_xor_sync(0xffffffffu, sl, 2);
        sh += __shfl_xor_sync(0xffffffffu, sh, 1);
        sh += __shfl_xor_sync(0xffffffffu, sh, 2);
        float pl = fast_exp(sl), ph = fast_exp(sh);
        l_lo += pl; l_hi += ph;
        const float2* vlo = (const float2*)(v + (base + rlo) * Dc);
        const float2* vhi = (const float2*)(v + (base + rhi) * Dc);
        #pragma unroll
        for (int nb = 0; nb < 9; nb++) {
            float2 a = vlo[4 * nb + c];
            o[nb][0] += pl * a.x; o[nb][1] += pl * a.y;
            float2 b = vhi[4 * nb + c];
            o[nb][2] += ph * b.x; o[nb][3] += ph * b.y;
        }
    }

    float il = 1.f / l_lo, ih = 1.f / l_hi;
    if (qrow_lo < 2048) {
        float2* olo = (float2*)(out + (base + qrow_lo) * Dc);
        #pragma unroll
        for (int nb = 0; nb < 9; nb++)
            olo[4 * nb + c] = make_float2(o[nb][0] * il, o[nb][1] * il);
    }
    if (qrow_hi < 2048) {
        float2* ohi = (float2*)(out + (base + qrow_hi) * Dc);
        #pragma unroll
        for (int nb = 0; nb < 9; nb++)
            ohi[4 * nb + c] = make_float2(o[nb][2] * ih, o[nb][3] * ih);
    }
}

// ---------------------------------------------------------------------------
extern "C" void kernel_launch(void* const* d_in, const int* in_sizes, int n_in,
                              void* d_out, int out_size) {
    const float* q        = (const float*)d_in[0];
    const float* k        = (const float*)d_in[1];
    const float* v        = (const float*)d_in[2];
    const float* pos      = (const float*)d_in[3];
    const float* pos_orig = (const float*)d_in[4];
    const float* time_    = (const float*)d_in[5];
    const float* freqs    = (const float*)d_in[6];
    const float* t_freqs  = (const float*)d_in[7];
    const float* scale    = (const float*)d_in[8];
    float* out = (float*)d_out;

    prep_kernel<<<Bc * Hc * Sc / 8, 256>>>(q, k, pos, pos_orig, time_, freqs, t_freqs, scale, out);
    attn_kernel<<<dim3(12, 32), 256>>>(v, out);
}

// round 14
// speedup vs baseline: 1.0525x; 1.0525x over previous
#include <cuda_runtime.h>
#include <cstdint>
#include <math.h>

#define Bc 2
#define Hc 16
#define Sc 2048
#define Dc 72

static constexpr int NROWS = Bc * Hc * Sc;   // 65536

__device__ __align__(16) float g_q[(size_t)NROWS * Dc];
__device__ __align__(16) float g_k[(size_t)NROWS * Dc];

// ---------------------------------------------------------------------------
// helpers
// ---------------------------------------------------------------------------
__device__ __forceinline__ uint32_t f2tf(float x) {
    uint32_t r;
    asm("cvt.rna.tf32.f32 %0, %1;" : "=r"(r) : "f"(x));
    return r;
}
__device__ __forceinline__ uint32_t smem_u32(const void* p) {
    uint32_t a;
    asm("{ .reg .u64 t; cvta.to.shared.u64 t, %1; cvt.u32.u64 %0, t; }" : "=r"(a) : "l"(p));
    return a;
}
__device__ __forceinline__ void cp16(uint32_t dst, const void* src) {
    asm volatile("cp.async.cg.shared.global [%0], [%1], 16;" :: "r"(dst), "l"(src) : "memory");
}
#define CP_COMMIT() asm volatile("cp.async.commit_group;" ::: "memory")
#define CP_WAIT1()  asm volatile("cp.async.wait_group 1;" ::: "memory")
#define CP_WAIT0()  asm volatile("cp.async.wait_group 0;" ::: "memory")

// D += A(16x8,row) * B(8x8,col)   tf32, fp32 accum
__device__ __forceinline__ void mma8(float& d0, float& d1, float& d2, float& d3,
                                     uint32_t a0, uint32_t a1, uint32_t a2, uint32_t a3,
                                     uint32_t b0, uint32_t b1) {
    asm volatile("mma.sync.aligned.m16n8k8.row.col.f32.tf32.tf32.f32 "
                 "{%0,%1,%2,%3}, {%4,%5,%6,%7}, {%8,%9}, {%0,%1,%2,%3};"
                 : "+f"(d0), "+f"(d1), "+f"(d2), "+f"(d3)
                 : "r"(a0), "r"(a1), "r"(a2), "r"(a3), "r"(b0), "r"(b1));
}

// exp(s) for bounded |s|, FMA-pipe only (no MUFU). rel err ~2e-6.
__device__ __forceinline__ float fast_exp(float s) {
    const float L2E = 1.4426950408889634f;
    float x = s * L2E;
    int   ni = __float2int_rn(x);
    float f  = x - (float)ni;
    float p  = 0.0013333558f;
    p = fmaf(p, f, 0.0096181290f);
    p = fmaf(p, f, 0.0555041087f);
    p = fmaf(p, f, 0.2402265069f);
    p = fmaf(p, f, 0.6931471806f);
    p = fmaf(p, f, 1.0f);
    return p * __int_as_float((ni + 127) << 23);
}

// ---------------------------------------------------------------------------
// Preprocess: theta + rotary + L2 norm for q and k. One warp per (b,h,s) row.
// Also zeroes the output rows with s < 576 (no valid keys).
// ---------------------------------------------------------------------------
__global__ void prep_kernel(const float* __restrict__ q, const float* __restrict__ k,
                            const float* __restrict__ pos, const float* __restrict__ pos_orig,
                            const float* __restrict__ time_, const float* __restrict__ freqs,
                            const float* __restrict__ t_freqs, const float* __restrict__ scale,
                            float* __restrict__ out) {
    int warp = threadIdx.x >> 5, lane = threadIdx.x & 31;
    int row = blockIdx.x * 8 + warp;
    int s  = row & (Sc - 1);
    int bh = row >> 11;
    int h  = bh & (Hc - 1);
    int b  = bh >> 4;

    const float* qr = q + (size_t)row * Dc;
    const float* kr = k + (size_t)row * Dc;

    __shared__ float sq[8][Dc], sk[8][Dc];
    for (int e = lane; e < Dc; e += 32) { sq[warp][e] = qr[e]; sk[warp][e] = kr[e]; }
    __syncwarp();

    if (s < 576) {   // zero invalid output rows
        float4* orow = (float4*)(out + (size_t)row * Dc);
        if (lane < 18) orow[lane] = make_float4(0.f, 0.f, 0.f, 0.f);
    }

    int ps = (b * Sc + s) * 2;
    float px  = 2.f * pos[ps]       - 1.f;
    float py  = 2.f * pos[ps + 1]   - 1.f;
    float pxo = 2.f * pos_orig[ps]     - 1.f;
    float pyo = 2.f * pos_orig[ps + 1] - 1.f;
    float tm  = time_[b * Sc + s];

    float oq[3], ok[3];
    float ssq = 0.f, ssk = 0.f;
    #pragma unroll
    for (int slot = 0; slot < 3; slot++) {
        int j = lane + slot * 32;
        if (j < Dc) {
            float xq = sq[warp][j], xk = sk[warp][j];
            if (j < 60) {
                int jj = (j < 30) ? j : j - 30;
                int seg = jj / 6, i = jj % 6;
                float coef, fr;
                if      (seg == 0) { coef = pyo; fr = freqs[96 + h * 6 + i]; }
                else if (seg == 1) { coef = py;  fr = freqs[96 + h * 6 + i]; }
                else if (seg == 2) { coef = pxo; fr = freqs[h * 6 + i]; }
                else if (seg == 3) { coef = px;  fr = freqs[h * 6 + i]; }
                else               { coef = tm;  fr = t_freqs[h * 6 + i]; }
                float th = coef * fr, c, sn;
                sincosf(th, &sn, &c);
                if (j < 30) {
                    oq[slot] = xq * c - sq[warp][j + 30] * sn;
                    ok[slot] = xk * c - sk[warp][j + 30] * sn;
                } else {
                    oq[slot] = xq * c + sq[warp][j - 30] * sn;
                    ok[slot] = xk * c + sk[warp][j - 30] * sn;
                }
            } else { oq[slot] = xq; ok[slot] = xk; }
            ssq += oq[slot] * oq[slot];
            ssk += ok[slot] * ok[slot];
        } else { oq[slot] = 0.f; ok[slot] = 0.f; }
    }
    #pragma unroll
    for (int off = 16; off; off >>= 1) {
        ssq += __shfl_xor_sync(0xffffffffu, ssq, off);
        ssk += __shfl_xor_sync(0xffffffffu, ssk, off);
    }
    float ss = sqrtf(scale[h]);
    float rq = ss * rsqrtf(ssq + 1e-6f);
    float rk = ss * rsqrtf(ssk + 1e-6f);
    #pragma unroll
    for (int slot = 0; slot < 3; slot++) {
        int j = lane + slot * 32;
        if (j < Dc) {
            g_q[(size_t)row * Dc + j] = oq[slot] * rq;
            g_k[(size_t)row * Dc + j] = ok[slot] * rk;
        }
    }
}

// ---------------------------------------------------------------------------
// Attention: warp-level tf32 mma.sync, 64-query tiles, 128 threads (4 warps),
// grid 23 x 32. Double-buffered cp.async K/V (raw fp32 bits -> tf32 truncation).
// Bounded scores -> no softmax max. grid covers q in [576, 2048).
// ---------------------------------------------------------------------------
static constexpr int KVS = 76;                       // padded row stride (u32)
static constexpr int KTILE_U32 = 64 * KVS;           // 4864 u32 per K (or V) tile
static constexpr int STAGE_U32 = 2 * KTILE_U32;      // K + V per stage = 9728
static constexpr int SMEM_BYTES = 2 * STAGE_U32 * 4; // 77824 B

__global__ void __launch_bounds__(128)
attn_kernel(const float* __restrict__ v, float* __restrict__ out) {
    extern __shared__ uint32_t sm[];
    uint32_t smbase = smem_u32(sm);

    int tid = threadIdx.x, wid = tid >> 5, lane = tid & 31;
    int g = lane >> 2, c = lane & 3;
    int m  = blockIdx.x;                  // 0..22
    int bh = blockIdx.y;
    int q0 = 576 + 64 * m;
    size_t base = (size_t)bh * Sc;

    // ---- stage Q (into stage-0 area, before any cp.async), build A-frags ----
    {
        float4* qdst = (float4*)sm;
        const float4* qsrc = (const float4*)(g_q + (base + q0) * Dc);
        for (int i = tid; i < 64 * 18; i += 128) qdst[i] = qsrc[i];
    }
    __syncthreads();
    uint32_t aq[9][4];
    {
        const float* qb = (const float*)sm + (wid * 16) * 72;
        #pragma unroll
        for (int kb = 0; kb < 9; kb++) {
            aq[kb][0] = f2tf(qb[g * 72       + kb * 8 + c]);
            aq[kb][1] = f2tf(qb[(g + 8) * 72 + kb * 8 + c]);
            aq[kb][2] = f2tf(qb[g * 72       + kb * 8 + 4 + c]);
            aq[kb][3] = f2tf(qb[(g + 8) * 72 + kb * 8 + 4 + c]);
        }
    }
    __syncthreads();   // Q reads done before stage-0 cp.async overwrites

    int nt = (m < 8) ? (10 + m) : 17;

    // ---- prologue: async-load tile 0 into stage 0 ----
    {
        const float4* ksrc = (const float4*)(g_k + base * Dc);
        const float4* vsrc = (const float4*)(v   + base * Dc);
        #pragma unroll
        for (int j = 0; j < 9; j++) {
            int i = tid + j * 128;
            int r = i / 18, c4 = (i % 18) * 4;
            uint32_t off = (uint32_t)(r * KVS + c4) * 4u;
            cp16(smbase + off, ksrc + i);
            cp16(smbase + KTILE_U32 * 4u + off, vsrc + i);
        }
        CP_COMMIT();
    }

    float o[9][4];
    #pragma unroll
    for (int i = 0; i < 9; i++) { o[i][0] = o[i][1] = o[i][2] = o[i][3] = 0.f; }
    float l_lo = 0.f, l_hi = 0.f;
    int qrow_lo = q0 + wid * 16 + g;
    int qrow_hi = qrow_lo + 8;

    for (int kt = 0; kt < nt; kt++) {
        // prefetch tile kt+1 into the other stage, then wait for tile kt
        if (kt + 1 < nt) {
            uint32_t sb = smbase + (uint32_t)(((kt + 1) & 1) * STAGE_U32) * 4u;
            const float4* ksrc = (const float4*)(g_k + (base + (size_t)(kt + 1) * 64) * Dc);
            const float4* vsrc = (const float4*)(v   + (base + (size_t)(kt + 1) * 64) * Dc);
            #pragma unroll
            for (int j = 0; j < 9; j++) {
                int i = tid + j * 128;
                int r = i / 18, c4 = (i % 18) * 4;
                uint32_t off = (uint32_t)(r * KVS + c4) * 4u;
                cp16(sb + off, ksrc + i);
                cp16(sb + KTILE_U32 * 4u + off, vsrc + i);
            }
            CP_COMMIT();
            CP_WAIT1();
        } else {
            CP_WAIT0();
        }
        __syncthreads();

        const uint32_t* Ks = sm + (kt & 1) * STAGE_U32;
        const uint32_t* Vs = Ks + KTILE_U32;

        bool lastmask = (m < 8) && (kt == nt - 1);
        int kb_glob = kt * 64;

        #pragma unroll
        for (int nb = 0; nb < 8; nb++) {
            // S block: 16 q-rows x 8 keys, two independent accumulation chains
            float x0 = 0.f, x1 = 0.f, x2 = 0.f, x3 = 0.f;
            float y0 = 0.f, y1 = 0.f, y2 = 0.f, y3 = 0.f;
            const uint32_t* kbp = Ks + (nb * 8 + g) * KVS + c;
            #pragma unroll
            for (int kb = 0; kb < 9; kb += 2) {
                mma8(x0, x1, x2, x3, aq[kb][0], aq[kb][1], aq[kb][2], aq[kb][3],
                     kbp[kb * 8], kbp[kb * 8 + 4]);
                if (kb + 1 < 9)
                    mma8(y0, y1, y2, y3, aq[kb+1][0], aq[kb+1][1], aq[kb+1][2], aq[kb+1][3],
                         kbp[(kb+1) * 8], kbp[(kb+1) * 8 + 4]);
            }
            float p0 = fast_exp(x0 + y0), p1 = fast_exp(x1 + y1);
            float p2 = fast_exp(x2 + y2), p3 = fast_exp(x3 + y3);
            if (lastmask) {
                int col = kb_glob + nb * 8 + 2 * c;
                if (col     > qrow_lo) p0 = 0.f;
                if (col + 1 > qrow_lo) p1 = 0.f;
                if (col     > qrow_hi) p2 = 0.f;
                if (col + 1 > qrow_hi) p3 = 0.f;
            }
            l_lo += p0 + p1;
            l_hi += p2 + p3;

            // repack D-layout -> A-layout (P fragment) via shuffles
            int srcA = (lane & ~3) + (c >> 1);
            int srcB = srcA + 2;
            float v00 = __shfl_sync(0xffffffffu, p0, srcA);
            float v01 = __shfl_sync(0xffffffffu, p1, srcA);
            float v10 = __shfl_sync(0xffffffffu, p2, srcA);
            float v11 = __shfl_sync(0xffffffffu, p3, srcA);
            float w00 = __shfl_sync(0xffffffffu, p0, srcB);
            float w01 = __shfl_sync(0xffffffffu, p1, srcB);
            float w10 = __shfl_sync(0xffffffffu, p2, srcB);
            float w11 = __shfl_sync(0xffffffffu, p3, srcB);
            bool odd = (c & 1);
            uint32_t pa0 = __float_as_uint(odd ? v01 : v00);
            uint32_t pa1 = __float_as_uint(odd ? v11 : v10);
            uint32_t pa2 = __float_as_uint(odd ? w01 : w00);
            uint32_t pa3 = __float_as_uint(odd ? w11 : w10);

            // O += P(16x8keys) @ V(8keys x 72dims)
            const uint32_t* vbp = Vs + (nb * 8 + c) * KVS + g;
            #pragma unroll
            for (int db = 0; db < 9; db++) {
                mma8(o[db][0], o[db][1], o[db][2], o[db][3], pa0, pa1, pa2, pa3,
                     vbp[db * 8], vbp[4 * KVS + db * 8]);
            }
        }
        __syncthreads();
    }

    // reduce l across the 4 lanes sharing a row group
    l_lo += __shfl_xor_sync(0xffffffffu, l_lo, 1);
    l_lo += __shfl_xor_sync(0xffffffffu, l_lo, 2);
    l_hi += __shfl_xor_sync(0xffffffffu, l_hi, 1);
    l_hi += __shfl_xor_sync(0xffffffffu, l_hi, 2);

    if (m >= 8) {   // dense rows: add the self key k == q
        const float2* qlo = (const float2*)(g_q + (base + qrow_lo) * Dc);
        const float2* klo = (const float2*)(g_k + (base + qrow_lo) * Dc);
        const float2* qhi = (const float2*)(g_q + (base + qrow_hi) * Dc);
        const float2* khi = (const float2*)(g_k + (base + qrow_hi) * Dc);
        float sl = 0.f, sh = 0.f;
        #pragma unroll
        for (int nb = 0; nb < 9; nb++) {
            float2 a = qlo[4 * nb + c], b = klo[4 * nb + c];
            sl += a.x * b.x + a.y * b.y;
            float2 e = qhi[4 * nb + c], f = khi[4 * nb + c];
            sh += e.x * f.x + e.y * f.y;
        }
        sl += __shfl_xor_sync(0xffffffffu, sl, 1);
        sl += __shfl_xor_sync(0xffffffffu, sl, 2);
        sh += __shfl_xor_sync(0xffffffffu, sh, 1);
        sh += __shfl_xor_sync(0xffffffffu, sh, 2);
        float pl = fast_exp(sl), ph = fast_exp(sh);
        l_lo += pl; l_hi += ph;
        const float2* vlo = (const float2*)(v + (base + qrow_lo) * Dc);
        const float2* vhi = (const float2*)(v + (base + qrow_hi) * Dc);
        #pragma unroll
        for (int nb = 0; nb < 9; nb++) {
            float2 a = vlo[4 * nb + c];
            o[nb][0] += pl * a.x; o[nb][1] += pl * a.y;
            float2 b = vhi[4 * nb + c];
            o[nb][2] += ph * b.x; o[nb][3] += ph * b.y;
        }
    }

    float il = 1.f / l_lo, ih = 1.f / l_hi;
    float2* olo = (float2*)(out + (base + qrow_lo) * Dc);
    float2* ohi = (float2*)(out + (base + qrow_hi) * Dc);
    #pragma unroll
    for (int nb = 0; nb < 9; nb++) {
        olo[4 * nb + c] = make_float2(o[nb][0] * il, o[nb][1] * il);
        ohi[4 * nb + c] = make_float2(o[nb][2] * ih, o[nb][3] * ih);
    }
}

// ---------------------------------------------------------------------------
extern "C" void kernel_launch(void* const* d_in, const int* in_sizes, int n_in,
                              void* d_out, int out_size) {
    const float* q        = (const float*)d_in[0];
    const float* k        = (const float*)d_in[1];
    const float* v        = (const float*)d_in[2];
    const float* pos      = (const float*)d_in[3];
    const float* pos_orig = (const float*)d_in[4];
    const float* time_    = (const float*)d_in[5];
    const float* freqs    = (const float*)d_in[6];
    const float* t_freqs  = (const float*)d_in[7];
    const float* scale    = (const float*)d_in[8];
    float* out = (float*)d_out;

    cudaFuncSetAttribute(attn_kernel, cudaFuncAttributeMaxDynamicSharedMemorySize, SMEM_BYTES);

    prep_kernel<<<Bc * Hc * Sc / 8, 256>>>(q, k, pos, pos_orig, time_, freqs, t_freqs, scale, out);
    attn_kernel<<<dim3(23, 32), 128, SMEM_BYTES>>>(v, out);
}

// round 16
// speedup vs baseline: 1.0841x; 1.0300x over previous
#include <cuda_runtime.h>
#include <cstdint>
#include <math.h>

#define Bc 2
#define Hc 16
#define Sc 2048
#define Dc 72

static constexpr int NROWS = Bc * Hc * Sc;   // 65536

__device__ __align__(16) float g_q[(size_t)NROWS * Dc];
__device__ __align__(16) float g_k[(size_t)NROWS * Dc];
__device__ __align__(16) float g_v[(size_t)NROWS * Dc];

// ---------------------------------------------------------------------------
// helpers
// ---------------------------------------------------------------------------
__device__ __forceinline__ uint32_t f2tf(float x) {
    uint32_t r;
    asm("cvt.rna.tf32.f32 %0, %1;" : "=r"(r) : "f"(x));
    return r;
}
__device__ __forceinline__ uint32_t smem_u32(const void* p) {
    uint32_t a;
    asm("{ .reg .u64 t; cvta.to.shared.u64 t, %1; cvt.u32.u64 %0, t; }" : "=r"(a) : "l"(p));
    return a;
}
__device__ __forceinline__ void cp16(uint32_t dst, const void* src) {
    asm volatile("cp.async.cg.shared.global [%0], [%1], 16;" :: "r"(dst), "l"(src) : "memory");
}
#define CP_COMMIT() asm volatile("cp.async.commit_group;" ::: "memory")
#define CP_WAIT1()  asm volatile("cp.async.wait_group 1;" ::: "memory")
#define CP_WAIT0()  asm volatile("cp.async.wait_group 0;" ::: "memory")

// D += A(16x8,row) * B(8x8,col)   tf32, fp32 accum
__device__ __forceinline__ void mma8(float& d0, float& d1, float& d2, float& d3,
                                     uint32_t a0, uint32_t a1, uint32_t a2, uint32_t a3,
                                     uint32_t b0, uint32_t b1) {
    asm volatile("mma.sync.aligned.m16n8k8.row.col.f32.tf32.tf32.f32 "
                 "{%0,%1,%2,%3}, {%4,%5,%6,%7}, {%8,%9}, {%0,%1,%2,%3};"
                 : "+f"(d0), "+f"(d1), "+f"(d2), "+f"(d3)
                 : "r"(a0), "r"(a1), "r"(a2), "r"(a3), "r"(b0), "r"(b1));
}

// exp(s) for bounded |s|, FMA-pipe only (no MUFU). rel err ~2e-6.
__device__ __forceinline__ float fast_exp(float s) {
    const float L2E = 1.4426950408889634f;
    float x = s * L2E;
    int   ni = __float2int_rn(x);
    float f  = x - (float)ni;
    float p  = 0.0013333558f;
    p = fmaf(p, f, 0.0096181290f);
    p = fmaf(p, f, 0.0555041087f);
    p = fmaf(p, f, 0.2402265069f);
    p = fmaf(p, f, 0.6931471806f);
    p = fmaf(p, f, 1.0f);
    return p * __int_as_float((ni + 127) << 23);
}

// ---------------------------------------------------------------------------
// Preprocess: theta + rotary + L2 norm for q,k. One warp per (b,h,s) row.
// K and V are stored PRE-ROUNDED to tf32 (rna) so attn can cp.async raw bits.
// Also zeroes output rows with s < 576.
// ---------------------------------------------------------------------------
__global__ void prep_kernel(const float* __restrict__ q, const float* __restrict__ k,
                            const float* __restrict__ v,
                            const float* __restrict__ pos, const float* __restrict__ pos_orig,
                            const float* __restrict__ time_, const float* __restrict__ freqs,
                            const float* __restrict__ t_freqs, const float* __restrict__ scale,
                            float* __restrict__ out) {
    int warp = threadIdx.x >> 5, lane = threadIdx.x & 31;
    int row = blockIdx.x * 8 + warp;
    int s  = row & (Sc - 1);
    int bh = row >> 11;
    int h  = bh & (Hc - 1);
    int b  = bh >> 4;

    const float* qr = q + (size_t)row * Dc;
    const float* kr = k + (size_t)row * Dc;
    const float* vr = v + (size_t)row * Dc;

    __shared__ float sq[8][Dc], sk[8][Dc];
    for (int e = lane; e < Dc; e += 32) { sq[warp][e] = qr[e]; sk[warp][e] = kr[e]; }
    __syncwarp();

    if (s < 576) {   // zero invalid output rows
        float4* orow = (float4*)(out + (size_t)row * Dc);
        if (lane < 18) orow[lane] = make_float4(0.f, 0.f, 0.f, 0.f);
    }

    int ps = (b * Sc + s) * 2;
    float px  = 2.f * pos[ps]       - 1.f;
    float py  = 2.f * pos[ps + 1]   - 1.f;
    float pxo = 2.f * pos_orig[ps]     - 1.f;
    float pyo = 2.f * pos_orig[ps + 1] - 1.f;
    float tm  = time_[b * Sc + s];

    float oq[3], ok[3];
    float ssq = 0.f, ssk = 0.f;
    #pragma unroll
    for (int slot = 0; slot < 3; slot++) {
        int j = lane + slot * 32;
        if (j < Dc) {
            float xq = sq[warp][j], xk = sk[warp][j];
            if (j < 60) {
                int jj = (j < 30) ? j : j - 30;
                int seg = jj / 6, i = jj % 6;
                float coef, fr;
                if      (seg == 0) { coef = pyo; fr = freqs[96 + h * 6 + i]; }
                else if (seg == 1) { coef = py;  fr = freqs[96 + h * 6 + i]; }
                else if (seg == 2) { coef = pxo; fr = freqs[h * 6 + i]; }
                else if (seg == 3) { coef = px;  fr = freqs[h * 6 + i]; }
                else               { coef = tm;  fr = t_freqs[h * 6 + i]; }
                float th = coef * fr, c, sn;
                sincosf(th, &sn, &c);
                if (j < 30) {
                    oq[slot] = xq * c - sq[warp][j + 30] * sn;
                    ok[slot] = xk * c - sk[warp][j + 30] * sn;
                } else {
                    oq[slot] = xq * c + sq[warp][j - 30] * sn;
                    ok[slot] = xk * c + sk[warp][j - 30] * sn;
                }
            } else { oq[slot] = xq; ok[slot] = xk; }
            ssq += oq[slot] * oq[slot];
            ssk += ok[slot] * ok[slot];
        } else { oq[slot] = 0.f; ok[slot] = 0.f; }
    }
    #pragma unroll
    for (int off = 16; off; off >>= 1) {
        ssq += __shfl_xor_sync(0xffffffffu, ssq, off);
        ssk += __shfl_xor_sync(0xffffffffu, ssk, off);
    }
    float ss = sqrtf(scale[h]);
    float rq = ss * rsqrtf(ssq + 1e-6f);
    float rk = ss * rsqrtf(ssk + 1e-6f);
    #pragma unroll
    for (int slot = 0; slot < 3; slot++) {
        int j = lane + slot * 32;
        if (j < Dc) {
            g_q[(size_t)row * Dc + j] = oq[slot] * rq;                              // fp32 (rna at frag build)
            g_k[(size_t)row * Dc + j] = __uint_as_float(f2tf(ok[slot] * rk));       // pre-rounded tf32
            g_v[(size_t)row * Dc + j] = __uint_as_float(f2tf(vr[j]));               // pre-rounded tf32
        }
    }
}

// ---------------------------------------------------------------------------
// Attention: warp-level tf32 mma.sync. 128-query tiles, 256 threads (8 warps),
// 32-key double-buffered cp.async stages -> 38.9KB smem, 2 CTAs/SM (16 warps).
// grid = (12 q-tiles from q=576, 32 bh). Bounded scores -> no softmax max.
// ---------------------------------------------------------------------------
static constexpr int KVS = 76;                       // padded row stride (u32)
static constexpr int KTILE_U32 = 32 * KVS;           // 2432 u32 per 32-key tensor tile
static constexpr int STAGE_U32 = 2 * KTILE_U32;      // K + V per stage = 4864
// total static smem = 2 * STAGE_U32 * 4 = 38912 B; Q staging (36864 B) overlaps

__global__ void __launch_bounds__(256, 2)
attn_kernel(float* __restrict__ out) {
    __shared__ uint32_t sm[2 * STAGE_U32];
    uint32_t smbase = smem_u32(sm);

    int tid = threadIdx.x, wid = tid >> 5, lane = tid & 31;
    int g = lane >> 2, c = lane & 3;
    int m  = blockIdx.x;                  // 0..11
    int bh = blockIdx.y;
    int q0 = 576 + 128 * m;
    size_t base = (size_t)bh * Sc;

    // ---- stage Q (128 rows, clamped for the m=11 tail), build A-fragments ----
    {
        float4* qdst = (float4*)sm;
        for (int i = tid; i < 128 * 18; i += 256) {
            int r = i / 18, cc = i % 18;
            int qr = q0 + r; if (qr > 2047) qr = 2047;
            qdst[i] = ((const float4*)(g_q + (base + qr) * Dc))[cc];
        }
    }
    __syncthreads();
    uint32_t aq[9][4];
    {
        const float* qb = (const float*)sm + (wid * 16) * 72;
        #pragma unroll
        for (int kb = 0; kb < 9; kb++) {
            aq[kb][0] = f2tf(qb[g * 72       + kb * 8 + c]);
            aq[kb][1] = f2tf(qb[(g + 8) * 72 + kb * 8 + c]);
            aq[kb][2] = f2tf(qb[g * 72       + kb * 8 + 4 + c]);
            aq[kb][3] = f2tf(qb[(g + 8) * 72 + kb * 8 + 4 + c]);
        }
    }
    __syncthreads();   // Q reads done before stage-0 cp.async overwrites

    bool causal = (m < 4);
    int nt = causal ? (22 + 4 * m) : 34;     // 32-key tiles

    // ---- prologue: async-load tile 0 into stage 0 ----
    {
        const float4* ksrc = (const float4*)(g_k + base * Dc);
        const float4* vsrc = (const float4*)(g_v + base * Dc);
        for (int i = tid; i < 32 * 18; i += 256) {
            int r = i / 18, c4 = (i % 18) * 4;
            uint32_t off = (uint32_t)(r * KVS + c4) * 4u;
            cp16(smbase + off, ksrc + i);
            cp16(smbase + KTILE_U32 * 4u + off, vsrc + i);
        }
        CP_COMMIT();
    }

    float o[9][4];
    #pragma unroll
    for (int i = 0; i < 9; i++) { o[i][0] = o[i][1] = o[i][2] = o[i][3] = 0.f; }
    float l_lo = 0.f, l_hi = 0.f;
    int qrow_lo = q0 + wid * 16 + g;
    int qrow_hi = qrow_lo + 8;

    for (int kt = 0; kt < nt; kt++) {
        // prefetch tile kt+1 into the other stage, then wait for tile kt
        if (kt + 1 < nt) {
            uint32_t sb = smbase + (uint32_t)(((kt + 1) & 1) * STAGE_U32) * 4u;
            const float4* ksrc = (const float4*)(g_k + (base + (size_t)(kt + 1) * 32) * Dc);
            const float4* vsrc = (const float4*)(g_v + (base + (size_t)(kt + 1) * 32) * Dc);
            for (int i = tid; i < 32 * 18; i += 256) {
                int r = i / 18, c4 = (i % 18) * 4;
                uint32_t off = (uint32_t)(r * KVS + c4) * 4u;
                cp16(sb + off, ksrc + i);
                cp16(sb + KTILE_U32 * 4u + off, vsrc + i);
            }
            CP_COMMIT();
            CP_WAIT1();
        } else {
            CP_WAIT0();
        }
        __syncthreads();

        const uint32_t* Ks = sm + (kt & 1) * STAGE_U32;
        const uint32_t* Vs = Ks + KTILE_U32;

        bool lastmask = causal && (kt >= nt - 4);   // diagonal spans last 4 tiles
        int kb_glob = kt * 32;

        #pragma unroll
        for (int nb = 0; nb < 4; nb++) {
            // S block: 16 q-rows x 8 keys, two independent accumulation chains
            float x0 = 0.f, x1 = 0.f, x2 = 0.f, x3 = 0.f;
            float y0 = 0.f, y1 = 0.f, y2 = 0.f, y3 = 0.f;
            const uint32_t* kbp = Ks + (nb * 8 + g) * KVS + c;
            #pragma unroll
            for (int kb = 0; kb < 9; kb += 2) {
                mma8(x0, x1, x2, x3, aq[kb][0], aq[kb][1], aq[kb][2], aq[kb][3],
                     kbp[kb * 8], kbp[kb * 8 + 4]);
                if (kb + 1 < 9)
                    mma8(y0, y1, y2, y3, aq[kb+1][0], aq[kb+1][1], aq[kb+1][2], aq[kb+1][3],
                         kbp[(kb+1) * 8], kbp[(kb+1) * 8 + 4]);
            }
            float p0 = fast_exp(x0 + y0), p1 = fast_exp(x1 + y1);
            float p2 = fast_exp(x2 + y2), p3 = fast_exp(x3 + y3);
            if (lastmask) {
                int col = kb_glob + nb * 8 + 2 * c;
                if (col     > qrow_lo) p0 = 0.f;
                if (col + 1 > qrow_lo) p1 = 0.f;
                if (col     > qrow_hi) p2 = 0.f;
                if (col + 1 > qrow_hi) p3 = 0.f;
            }
            l_lo += p0 + p1;
            l_hi += p2 + p3;

            // repack D-layout -> A-layout (P fragment) via shuffles
            int srcA = (lane & ~3) + (c >> 1);
            int srcB = srcA + 2;
            float v00 = __shfl_sync(0xffffffffu, p0, srcA);
            float v01 = __shfl_sync(0xffffffffu, p1, srcA);
            float v10 = __shfl_sync(0xffffffffu, p2, srcA);
            float v11 = __shfl_sync(0xffffffffu, p3, srcA);
            float w00 = __shfl_sync(0xffffffffu, p0, srcB);
            float w01 = __shfl_sync(0xffffffffu, p1, srcB);
            float w10 = __shfl_sync(0xffffffffu, p2, srcB);
            float w11 = __shfl_sync(0xffffffffu, p3, srcB);
            bool odd = (c & 1);
            uint32_t pa0 = __float_as_uint(odd ? v01 : v00);
            uint32_t pa1 = __float_as_uint(odd ? v11 : v10);
            uint32_t pa2 = __float_as_uint(odd ? w01 : w00);
            uint32_t pa3 = __float_as_uint(odd ? w11 : w10);

            // O += P(16x8keys) @ V(8keys x 72dims)
            const uint32_t* vbp = Vs + (nb * 8 + c) * KVS + g;
            #pragma unroll
            for (int db = 0; db < 9; db++) {
                mma8(o[db][0], o[db][1], o[db][2], o[db][3], pa0, pa1, pa2, pa3,
                     vbp[db * 8], vbp[4 * KVS + db * 8]);
            }
        }
        __syncthreads();
    }

    // reduce l across the 4 lanes sharing a row group
    l_lo += __shfl_xor_sync(0xffffffffu, l_lo, 1);
    l_lo += __shfl_xor_sync(0xffffffffu, l_lo, 2);
    l_hi += __shfl_xor_sync(0xffffffffu, l_hi, 1);
    l_hi += __shfl_xor_sync(0xffffffffu, l_hi, 2);

    if (!causal) {   // dense rows: add the self key k == q
        int rlo = (qrow_lo < 2048) ? qrow_lo : 2047;
        int rhi = (qrow_hi < 2048) ? qrow_hi : 2047;
        const float2* qlo = (const float2*)(g_q + (base + rlo) * Dc);
        const float2* klo = (const float2*)(g_k + (base + rlo) * Dc);
        const float2* qhi = (const float2*)(g_q + (base + rhi) * Dc);
        const float2* khi = (const float2*)(g_k + (base + rhi) * Dc);
        float sl = 0.f, sh = 0.f;
        #pragma unroll
        for (int nb = 0; nb < 9; nb++) {
            float2 a = qlo[4 * nb + c], b = klo[4 * nb + c];
            sl += a.x * b.x + a.y * b.y;
            float2 e = qhi[4 * nb + c], f = khi[4 * nb + c];
            sh += e.x * f.x + e.y * f.y;
        }
        sl += __shfl_xor_sync(0xffffffffu, sl, 1);
        sl += __shfl_xor_sync(0xffffffffu, sl, 2);
        sh += __shfl_xor_sync(0xffffffffu, sh, 1);
        sh += __shfl_xor_sync(0xffffffffu, sh, 2);
        float pl = fast_exp(sl), ph = fast_exp(sh);
        l_lo += pl; l_hi += ph;
        const float2* vlo = (const float2*)(g_v + (base + rlo) * Dc);
        const float2* vhi = (const float2*)(g_v + (base + rhi) * Dc);
        #pragma unroll
        for (int nb = 0; nb < 9; nb++) {
            float2 a = vlo[4 * nb + c];
            o[nb][0] += pl * a.x; o[nb][1] += pl * a.y;
            float2 b = vhi[4 * nb + c];
            o[nb][2] += ph * b.x; o[nb][3] += ph * b.y;
        }
    }

    float il = 1.f / l_lo, ih = 1.f / l_hi;
    if (qrow_lo < 2048) {
        float2* olo = (float2*)(out + (base + qrow_lo) * Dc);
        #pragma unroll
        for (int nb = 0; nb < 9; nb++)
            olo[4 * nb + c] = make_float2(o[nb][0] * il, o[nb][1] * il);
    }
    if (qrow_hi < 2048) {
        float2* ohi = (float2*)(out + (base + qrow_hi) * Dc);
        #pragma unroll
        for (int nb = 0; nb < 9; nb++)
            ohi[4 * nb + c] = make_float2(o[nb][2] * ih, o[nb][3] * ih);
    }
}

// ---------------------------------------------------------------------------
extern "C" void kernel_launch(void* const* d_in, const int* in_sizes, int n_in,
                              void* d_out, int out_size) {
    const float* q        = (const float*)d_in[0];
    const float* k        = (const float*)d_in[1];
    const float* v        = (const float*)d_in[2];
    const float* pos      = (const float*)d_in[3];
    const float* pos_orig = (const float*)d_in[4];
    const float* time_    = (const float*)d_in[5];
    const float* freqs    = (const float*)d_in[6];
    const float* t_freqs  = (const float*)d_in[7];
    const float* scale    = (const float*)d_in[8];
    float* out = (float*)d_out;

    prep_kernel<<<Bc * Hc * Sc / 8, 256>>>(q, k, v, pos, pos_orig, time_, freqs, t_freqs, scale, out);
    attn_kernel<<<dim3(12, 32), 256>>>(out);
}